// round 15
// baseline (speedup 1.0000x reference)
#include <cuda_runtime.h>
#include <cuda_fp16.h>
#include <cstdint>

// out[n,m,o] = sum_k sum_f x[n, idx[m,k], f] * iv[m,k] * W[k,f,o] + bias[o]
// N=16, M=65536, FIN=FOUT=32, K=7
static constexpr int N_ = 16, M_ = 65536, K_ = 7;
static constexpr int TILE_R = 64;             // rows per CTA (16 per warp)
static constexpr int NPC = 4;                 // n values per CTA

__device__ __forceinline__ uint32_t smem_u32(const void* p) {
    uint32_t a;
    asm("{ .reg .u64 t; cvta.to.shared.u64 t, %1; cvt.u32.u64 %0, t; }" : "=r"(a) : "l"(p));
    return a;
}
// pack two f32 -> f16x2 (first arg -> bits[15:0], second -> bits[31:16]), round-nearest
__device__ __forceinline__ uint32_t pack_f16x2(float lo_half, float hi_half) {
    uint32_t r;
    asm("cvt.rn.f16x2.f32 %0, %1, %2;" : "=r"(r) : "f"(hi_half), "f"(lo_half));
    return r;
}
__device__ __forceinline__ void ldmBT(uint32_t* r, uint32_t addr) {
    asm volatile("ldmatrix.sync.aligned.m8n8.x4.trans.shared.b16 {%0,%1,%2,%3}, [%4];"
                 : "=r"(r[0]), "=r"(r[1]), "=r"(r[2]), "=r"(r[3]) : "r"(addr));
}
__device__ __forceinline__ void mma16816(float* c, const uint32_t* a, uint32_t b0, uint32_t b1) {
    asm volatile(
        "mma.sync.aligned.m16n8k16.row.col.f32.f16.f16.f32 "
        "{%0,%1,%2,%3}, {%4,%5,%6,%7}, {%8,%9}, {%0,%1,%2,%3};"
        : "+f"(c[0]), "+f"(c[1]), "+f"(c[2]), "+f"(c[3])
        : "r"(a[0]), "r"(a[1]), "r"(a[2]), "r"(a[3]), "r"(b0), "r"(b1));
}
// B storage-row permutation (verified R7): storage row r holds W f:
__device__ __forceinline__ int fperm(int r) {
    const int b = r & 15;
    return (r & 16) + 4 * ((b & 7) >> 1) + 2 * (b >> 3) + (b & 1);
}

__global__ void __launch_bounds__(128, 6)
gfc_hmma_kernel(const float* __restrict__ x,
                const float* __restrict__ w,
                const float* __restrict__ bias,
                const int*   __restrict__ idxl,
                const float* __restrict__ ivv,
                float*       __restrict__ out)
{
    __shared__ __align__(128) uint8_t Bsm[K_ * 2560];   // per k: 32 krows x 80B fp16
    __shared__ int2 sPair[TILE_R * K_];                 // (idx<<3, iv) pairs

    const int tid = threadIdx.x;
    const int wid = tid >> 5;
    const int lan = tid & 31;
    const int q   = lan >> 2;     // fragment row quad
    const int c   = lan & 3;      // fragment k-group
    const int m0  = blockIdx.x * TILE_R;

    // --- stage (idx*8, iv) pairs (once, reused for all NPC n-values) ---
    for (int i = tid; i < TILE_R * K_; i += 128)
        sPair[i] = make_int2(idxl[m0 * K_ + i] << 3, __float_as_int(ivv[m0 * K_ + i]));

    // --- stage B with k-permuted storage rows; packed 32-bit stores ---
    for (int i = tid; i < K_ * 512; i += 128) {
        const int k = i >> 9, r = (i >> 4) & 31, op = i & 15;   // op = o-pair
        const float* wr = w + (k << 10) + fperm(r) * 32 + op * 2;
        *(uint32_t*)(Bsm + k * 2560 + r * 80 + op * 4) = pack_f16x2(wr[0], wr[1]);
    }
    __syncthreads();   // only CTA-wide barrier

    const uint32_t bbase = smem_u32(Bsm);
    const float4* x4 = reinterpret_cast<const float4*>(x);
    const int rbase = (wid << 4) + q;      // local rows: rbase, rbase+8
    const int nc0 = (lan >> 4) << 3;
    const int krow = lan & 15;
    const int n0 = blockIdx.y * NPC;

    // bias fragment (n-invariant)
    float2 bv[4];
    const float2* b2 = reinterpret_cast<const float2*>(bias);
    #pragma unroll
    for (int nt = 0; nt < 4; ++nt) bv[nt] = __ldg(b2 + nt * 4 + c);

    // ---- prologue: pairs + full gather for (j=0, k=0) ----
    int2 pr[2];
    float4 g[2][2];
    {
        const int xb = n0 * (M_ * 8);
        #pragma unroll
        for (int t = 0; t < 2; ++t) {
            pr[t] = sPair[(rbase + (t << 3)) * K_ + 0];
            const float4* p = x4 + xb + pr[t].x;
            g[t][0] = __ldg(p + c);
            g[t][1] = __ldg(p + 4 + c);
        }
    }

    #pragma unroll 1
    for (int j = 0; j < NPC; ++j) {
        float acc[4][4];
        #pragma unroll
        for (int nt = 0; nt < 4; ++nt)
            #pragma unroll
            for (int e = 0; e < 4; ++e)
                acc[nt][e] = 0.f;

        #pragma unroll 1
        for (int k = 0; k < K_; ++k) {
            // scales for current (j,k); pr.x already consumed by the gather
            float s0 = __int_as_float(pr[0].y);
            float s1 = __int_as_float(pr[1].y);

            // next iteration coordinates (clamped refetch at the very end)
            const bool last = (k == K_ - 1);
            const int  kn = last ? 0 : k + 1;
            const int  jn = last ? ((j + 1 < NPC) ? j + 1 : j) : j;
            const int  xbn = (n0 + jn) * (M_ * 8);

            const uint32_t bk = bbase + k * 2560;

            // ---- phase cc0 ----
            uint32_t Ba[4], Bb[4];
            ldmBT(Ba, bk + krow * 80 + nc0 * 2);               // cc0, n 0..15
            ldmBT(Bb, bk + krow * 80 + (16 + nc0) * 2);        // cc0, n 16..31
            uint32_t a0[4];
            a0[0] = pack_f16x2(g[0][0].x * s0, g[0][0].y * s0);
            a0[1] = pack_f16x2(g[1][0].x * s1, g[1][0].y * s1);
            a0[2] = pack_f16x2(g[0][0].z * s0, g[0][0].w * s0);
            a0[3] = pack_f16x2(g[1][0].z * s1, g[1][0].w * s1);
            // advance pairs to next (j,k), prefetch lower-half gather into freed g[.][0]
            #pragma unroll
            for (int t = 0; t < 2; ++t)
                pr[t] = sPair[(rbase + (t << 3)) * K_ + kn];
            #pragma unroll
            for (int t = 0; t < 2; ++t)
                g[t][0] = __ldg(x4 + xbn + pr[t].x + c);
            mma16816(acc[0], a0, Ba[0], Ba[1]);
            mma16816(acc[1], a0, Ba[2], Ba[3]);
            mma16816(acc[2], a0, Bb[0], Bb[1]);
            mma16816(acc[3], a0, Bb[2], Bb[3]);

            // ---- phase cc1 ----
            uint32_t Bc[4], Bd[4];
            ldmBT(Bc, bk + (16 + krow) * 80 + nc0 * 2);        // cc1, n 0..15
            ldmBT(Bd, bk + (16 + krow) * 80 + (16 + nc0) * 2); // cc1, n 16..31
            uint32_t a1[4];
            a1[0] = pack_f16x2(g[0][1].x * s0, g[0][1].y * s0);
            a1[1] = pack_f16x2(g[1][1].x * s1, g[1][1].y * s1);
            a1[2] = pack_f16x2(g[0][1].z * s0, g[0][1].w * s0);
            a1[3] = pack_f16x2(g[1][1].z * s1, g[1][1].w * s1);
            // prefetch upper-half gather into freed g[.][1]
            #pragma unroll
            for (int t = 0; t < 2; ++t)
                g[t][1] = __ldg(x4 + xbn + pr[t].x + 4 + c);
            mma16816(acc[0], a1, Bc[0], Bc[1]);
            mma16816(acc[1], a1, Bc[2], Bc[3]);
            mma16816(acc[2], a1, Bd[0], Bd[1]);
            mma16816(acc[3], a1, Bd[2], Bd[3]);
        }

        // --- epilogue for this n (next j's k=0 gather already in flight) ---
        const int n = n0 + j;
        const int r0 = m0 + (wid << 4) + q;
        #pragma unroll
        for (int nt = 0; nt < 4; ++nt) {
            float2 v0, v1;
            v0.x = acc[nt][0] + bv[nt].x;
            v0.y = acc[nt][1] + bv[nt].y;
            v1.x = acc[nt][2] + bv[nt].x;
            v1.y = acc[nt][3] + bv[nt].y;
            const int col = nt * 8 + c * 2;
            *reinterpret_cast<float2*>(out + ((size_t)(n * M_ + r0)) * 32 + col)     = v0;
            *reinterpret_cast<float2*>(out + ((size_t)(n * M_ + r0 + 8)) * 32 + col) = v1;
        }
    }
}

extern "C" void kernel_launch(void* const* d_in, const int* in_sizes, int n_in,
                              void* d_out, int out_size)
{
    const float* x    = (const float*)d_in[0];   // (16, 65536, 32) f32
    const float* wgt  = (const float*)d_in[1];   // (7, 32, 32) f32
    const float* bias = (const float*)d_in[2];   // (32,) f32
    const int*   idx  = (const int*)  d_in[3];   // (65536*7,) i32
    const float* iv   = (const float*)d_in[4];   // (65536, 7) f32
    float* out = (float*)d_out;                  // (16, 65536, 32) f32

    dim3 grid(M_ / TILE_R, N_ / NPC, 1);         // (1024, 4)
    gfc_hmma_kernel<<<grid, 128>>>(x, wgt, bias, idx, iv, out);
}

// round 16
// speedup vs baseline: 1.2383x; 1.2383x over previous
#include <cuda_runtime.h>
#include <cuda_fp16.h>
#include <cstdint>

// out[n,m,o] = sum_k sum_f x[n, idx[m,k], f] * iv[m,k] * W[k,f,o] + bias[o]
// N=16, M=65536, FIN=FOUT=32, K=7
static constexpr int N_ = 16, M_ = 65536, K_ = 7;
static constexpr int TILE_R = 128;
static constexpr int NPC = 4;                 // n values per CTA

__device__ __forceinline__ uint32_t smem_u32(const void* p) {
    uint32_t a;
    asm("{ .reg .u64 t; cvta.to.shared.u64 t, %1; cvt.u32.u64 %0, t; }" : "=r"(a) : "l"(p));
    return a;
}
// pack two f32 -> f16x2 (first arg -> bits[15:0], second -> bits[31:16]), round-nearest
__device__ __forceinline__ uint32_t pack_f16x2(float lo_half, float hi_half) {
    uint32_t r;
    asm("cvt.rn.f16x2.f32 %0, %1, %2;" : "=r"(r) : "f"(hi_half), "f"(lo_half));
    return r;
}
__device__ __forceinline__ void ldmBT(uint32_t* r, uint32_t addr) {
    asm volatile("ldmatrix.sync.aligned.m8n8.x4.trans.shared.b16 {%0,%1,%2,%3}, [%4];"
                 : "=r"(r[0]), "=r"(r[1]), "=r"(r[2]), "=r"(r[3]) : "r"(addr));
}
__device__ __forceinline__ void mma16816(float* c, const uint32_t* a, uint32_t b0, uint32_t b1) {
    asm volatile(
        "mma.sync.aligned.m16n8k16.row.col.f32.f16.f16.f32 "
        "{%0,%1,%2,%3}, {%4,%5,%6,%7}, {%8,%9}, {%0,%1,%2,%3};"
        : "+f"(c[0]), "+f"(c[1]), "+f"(c[2]), "+f"(c[3])
        : "r"(a[0]), "r"(a[1]), "r"(a[2]), "r"(a[3]), "r"(b0), "r"(b1));
}
// B storage-row permutation (verified R7): storage row r holds W f:
__device__ __forceinline__ int fperm(int r) {
    const int b = r & 15;
    return (r & 16) + 4 * ((b & 7) >> 1) + 2 * (b >> 3) + (b & 1);
}

__global__ void __launch_bounds__(128, 5)
gfc_hmma_kernel(const float* __restrict__ x,
                const float* __restrict__ w,
                const float* __restrict__ bias,
                const int*   __restrict__ idxl,
                const float* __restrict__ ivv,
                float*       __restrict__ out)
{
    __shared__ __align__(128) uint8_t Bsm[K_ * 2560];   // per k: 32 krows x 80B fp16
    __shared__ int2 sPair[TILE_R * K_];                 // (idx<<3, iv) pairs

    const int tid = threadIdx.x;
    const int wid = tid >> 5;
    const int lan = tid & 31;
    const int q   = lan >> 2;     // fragment row quad
    const int c   = lan & 3;      // fragment k-group
    const int m0  = blockIdx.x * TILE_R;

    // --- stage (idx*8, iv) pairs (once, reused for all NPC n-values) ---
    #pragma unroll
    for (int i = tid; i < TILE_R * K_; i += 128)
        sPair[i] = make_int2(idxl[m0 * K_ + i] << 3, __float_as_int(ivv[m0 * K_ + i]));

    // --- stage B with k-permuted storage rows; packed 32-bit stores ---
    for (int i = tid; i < K_ * 512; i += 128) {
        const int k = i >> 9, r = (i >> 4) & 31, op = i & 15;   // op = o-pair
        const float* wr = w + (k << 10) + fperm(r) * 32 + op * 2;
        *(uint32_t*)(Bsm + k * 2560 + r * 80 + op * 4) = pack_f16x2(wr[0], wr[1]);
    }
    __syncthreads();   // only CTA-wide barrier

    const uint32_t bbase = smem_u32(Bsm);
    const float4* x4 = reinterpret_cast<const float4*>(x);
    const int rbase = (wid << 5) + q;      // local rows: rbase + 8t, t=0..3
    const int nc0 = (lan >> 4) << 3;
    const int krow = lan & 15;
    const int n0 = blockIdx.y * NPC;

    // bias fragment (n-invariant)
    float2 bv[4];
    const float2* b2 = reinterpret_cast<const float2*>(bias);
    #pragma unroll
    for (int nt = 0; nt < 4; ++nt) bv[nt] = __ldg(b2 + nt * 4 + c);

    // ---- prologue: pairs + full gather for (j=0, k=0) ----
    int2 pr[4];
    float4 g[4][2];
    {
        const int xb = n0 * (M_ * 8);
        #pragma unroll
        for (int t = 0; t < 4; ++t) {
            pr[t] = sPair[(rbase + (t << 3)) * K_ + 0];
            const float4* p = x4 + xb + pr[t].x;
            g[t][0] = __ldg(p + c);
            g[t][1] = __ldg(p + 4 + c);
        }
    }

    #pragma unroll 1
    for (int j = 0; j < NPC; ++j) {
        float acc[2][4][4];
        #pragma unroll
        for (int mt = 0; mt < 2; ++mt)
            #pragma unroll
            for (int nt = 0; nt < 4; ++nt)
                #pragma unroll
                for (int e = 0; e < 4; ++e)
                    acc[mt][nt][e] = 0.f;

        #pragma unroll 1
        for (int k = 0; k < K_; ++k) {
            // scales for current (j,k); pr.x already consumed by the gather
            float s[4];
            #pragma unroll
            for (int t = 0; t < 4; ++t) s[t] = __int_as_float(pr[t].y);

            // next iteration coordinates (clamped refetch at the very end)
            const bool last = (k == K_ - 1);
            const int  kn = last ? 0 : k + 1;
            const int  jn = last ? ((j + 1 < NPC) ? j + 1 : j) : j;
            const int  xbn = (n0 + jn) * (M_ * 8);

            const uint32_t bk = bbase + k * 2560;

            // ---- phase cc0 ----
            uint32_t Ba[4], Bb[4];
            ldmBT(Ba, bk + krow * 80 + nc0 * 2);               // cc0, n 0..15
            ldmBT(Bb, bk + krow * 80 + (16 + nc0) * 2);        // cc0, n 16..31
            uint32_t a0[2][4];
            #pragma unroll
            for (int mt = 0; mt < 2; ++mt) {
                const int t0 = 2 * mt, t1 = 2 * mt + 1;
                a0[mt][0] = pack_f16x2(g[t0][0].x * s[t0], g[t0][0].y * s[t0]);
                a0[mt][1] = pack_f16x2(g[t1][0].x * s[t1], g[t1][0].y * s[t1]);
                a0[mt][2] = pack_f16x2(g[t0][0].z * s[t0], g[t0][0].w * s[t0]);
                a0[mt][3] = pack_f16x2(g[t1][0].z * s[t1], g[t1][0].w * s[t1]);
            }
            // advance pairs to next (j,k), prefetch lower-half gather into freed g[.][0]
            #pragma unroll
            for (int t = 0; t < 4; ++t)
                pr[t] = sPair[(rbase + (t << 3)) * K_ + kn];
            #pragma unroll
            for (int t = 0; t < 4; ++t)
                g[t][0] = __ldg(x4 + xbn + pr[t].x + c);
            #pragma unroll
            for (int mt = 0; mt < 2; ++mt) {
                mma16816(acc[mt][0], a0[mt], Ba[0], Ba[1]);
                mma16816(acc[mt][1], a0[mt], Ba[2], Ba[3]);
                mma16816(acc[mt][2], a0[mt], Bb[0], Bb[1]);
                mma16816(acc[mt][3], a0[mt], Bb[2], Bb[3]);
            }

            // ---- phase cc1 ----
            uint32_t Bc[4], Bd[4];
            ldmBT(Bc, bk + (16 + krow) * 80 + nc0 * 2);        // cc1, n 0..15
            ldmBT(Bd, bk + (16 + krow) * 80 + (16 + nc0) * 2); // cc1, n 16..31
            uint32_t a1[2][4];
            #pragma unroll
            for (int mt = 0; mt < 2; ++mt) {
                const int t0 = 2 * mt, t1 = 2 * mt + 1;
                a1[mt][0] = pack_f16x2(g[t0][1].x * s[t0], g[t0][1].y * s[t0]);
                a1[mt][1] = pack_f16x2(g[t1][1].x * s[t1], g[t1][1].y * s[t1]);
                a1[mt][2] = pack_f16x2(g[t0][1].z * s[t0], g[t0][1].w * s[t0]);
                a1[mt][3] = pack_f16x2(g[t1][1].z * s[t1], g[t1][1].w * s[t1]);
            }
            // prefetch upper-half gather into freed g[.][1]
            #pragma unroll
            for (int t = 0; t < 4; ++t)
                g[t][1] = __ldg(x4 + xbn + pr[t].x + 4 + c);
            #pragma unroll
            for (int mt = 0; mt < 2; ++mt) {
                mma16816(acc[mt][0], a1[mt], Bc[0], Bc[1]);
                mma16816(acc[mt][1], a1[mt], Bc[2], Bc[3]);
                mma16816(acc[mt][2], a1[mt], Bd[0], Bd[1]);
                mma16816(acc[mt][3], a1[mt], Bd[2], Bd[3]);
            }
        }

        // --- epilogue for this n (next j's k=0 gather already in flight) ---
        const int n = n0 + j;
        #pragma unroll
        for (int mt = 0; mt < 2; ++mt) {
            const int r0 = m0 + (wid << 5) + mt * 16 + q;
            #pragma unroll
            for (int nt = 0; nt < 4; ++nt) {
                float2 v0, v1;
                v0.x = acc[mt][nt][0] + bv[nt].x;
                v0.y = acc[mt][nt][1] + bv[nt].y;
                v1.x = acc[mt][nt][2] + bv[nt].x;
                v1.y = acc[mt][nt][3] + bv[nt].y;
                const int col = nt * 8 + c * 2;
                *reinterpret_cast<float2*>(out + ((size_t)(n * M_ + r0)) * 32 + col)     = v0;
                *reinterpret_cast<float2*>(out + ((size_t)(n * M_ + r0 + 8)) * 32 + col) = v1;
            }
        }
    }
}

extern "C" void kernel_launch(void* const* d_in, const int* in_sizes, int n_in,
                              void* d_out, int out_size)
{
    const float* x    = (const float*)d_in[0];   // (16, 65536, 32) f32
    const float* wgt  = (const float*)d_in[1];   // (7, 32, 32) f32
    const float* bias = (const float*)d_in[2];   // (32,) f32
    const int*   idx  = (const int*)  d_in[3];   // (65536*7,) i32
    const float* iv   = (const float*)d_in[4];   // (65536, 7) f32
    float* out = (float*)d_out;                  // (16, 65536, 32) f32

    dim3 grid(M_ / TILE_R, N_ / NPC, 1);         // (512, 4)
    gfc_hmma_kernel<<<grid, 128>>>(x, wgt, bias, idx, iv, out);
}